// round 11
// baseline (speedup 1.0000x reference)
#include <cuda_runtime.h>
#include <cuda_fp16.h>
#include <mma.h>
#include <cstdint>

using namespace nvcuda;

#define T_ 4
#define B_ 16
#define C_ 256
#define N_ 1024
#define CN_ (C_*N_)          // 262144
#define BCN (B_*C_*N_)       // 4194304
#define TBCN (T_*BCN)        // 16777216
#define BHN (B_*8*N_)        // 131072
#define NBITS (T_*BHN)       // 524288 words per branch

// Scratch (device globals: allocation-free)
__device__ unsigned g_bits[4][NBITS]; // spike bitpacks: q,k,v, xs
__device__ float    g_kvm[T_*B_*8*1024]; // kv matrices: [t,b,h][32 d][32 e]
__device__ float    g_wt[C_*C_];      // p_w transposed
__device__ __align__(16) __half g_wsplit[3][2][C_*C_]; // fp16 2-term split of q/k/v W

__device__ __forceinline__ uint32_t smem_u32(const void* p) {
    return (uint32_t)__cvta_generic_to_shared(p);
}
__device__ __forceinline__ void cp_async16(uint32_t saddr, const void* g) {
    asm volatile("cp.async.ca.shared.global [%0], [%1], 16;" :: "r"(saddr), "l"(g));
}

// ===========================================================================
// One-shot: 2-term fp16 split of q/k/v weights (x ~ h1 + h2 to ~2^-22)
// ===========================================================================
__global__ __launch_bounds__(256)
void wsplit_kernel(const float* __restrict__ qw, const float* __restrict__ kw,
                   const float* __restrict__ vw)
{
    int idx = blockIdx.x * 256 + threadIdx.x;         // < 3*65536
    int proj = idx >> 16, e = idx & 65535;
    const float* W = proj == 0 ? qw : (proj == 1 ? kw : vw);
    float x = W[e];
    __half h1 = __float2half_rn(x);
    __half h2 = __float2half_rn(x - __half2float(h1));
    g_wsplit[proj][0][e] = h1;
    g_wsplit[proj][1][e] = h2;
}

// ===========================================================================
// Fully fused projection: GEMM(fp16 3-term, fp32-exact-class) + BN + LIF(T)
// + bitpack, g_y eliminated. Block owns a 128(o) x 64(n) tile for ALL T
// timesteps of one (b, proj); LIF membrane lives in persistent smem.
// Grid: (N/64, C/128, B*3).
// ===========================================================================
#define KS 32
#define NSLAB 8
#define LDW2 40                                     // 32 fp16 + 8 pad
#define LDX3 72                                     // 64 fp16 + 8 pad
#define LDST 68                                     // stage row (64 + 4 pad)
#define MEM_OFF 0
#define MEM_BYTES (128*64*4)                        // 32768 (persistent)
#define MAIN_OFF MEM_BYTES                          // union region base
#define WBUF_BYTES (2*128*LDW2*2)                   // 20480
#define XS_OFF (MAIN_OFF + 2*WBUF_BYTES)            // 73728
#define XS_BYTES (2*KS*LDX3*2)                      // 9216
#define BN_OFF (XS_OFF + XS_BYTES)                  // 82944
#define SMEM_GT (BN_OFF + 2*128*4)                  // 83968

__global__ __launch_bounds__(256, 2)
void gemm_lif_kernel(const float* __restrict__ X,
                     const float* __restrict__ qg, const float* __restrict__ qb,
                     const float* __restrict__ qm, const float* __restrict__ qv,
                     const float* __restrict__ kg, const float* __restrict__ kb,
                     const float* __restrict__ km, const float* __restrict__ kv,
                     const float* __restrict__ vg, const float* __restrict__ vb,
                     const float* __restrict__ vm, const float* __restrict__ vv)
{
    extern __shared__ __align__(16) char smem[];
    float* memst = (float*)(smem + MEM_OFF);          // [128][64] persistent
    __half* Xs = (__half*)(smem + XS_OFF);            // [2][KS][LDX3]
    float* stage = (float*)(smem + MAIN_OFF);         // [128][LDST] (overlaps WBUFs)
    float* ssc = (float*)(smem + BN_OFF);
    float* ssh = ssc + 128;

    const int tid = threadIdx.x, wid = tid >> 5;
    const int n0 = blockIdx.x * 64;
    const int m0 = blockIdx.y * 128;
    const int proj = blockIdx.z % 3;
    const int b = blockIdx.z / 3;

    const float* gamma = proj == 0 ? qg : (proj == 1 ? kg : vg);
    const float* beta  = proj == 0 ? qb : (proj == 1 ? kb : vb);
    const float* mean  = proj == 0 ? qm : (proj == 1 ? km : vm);
    const float* var   = proj == 0 ? qv : (proj == 1 ? kv : vv);
    const __half* W0 = g_wsplit[proj][0];
    const __half* W1 = g_wsplit[proj][1];

    const int wo = wid & 3;          // o-group (32 rows)
    const int wn = wid >> 2;         // n-group (32 cols)
    const uint32_t ws_base = smem_u32(smem) + MAIN_OFF;

    // init: BN params + zero membrane
    if (tid < 128) {
        float sc = gamma[m0 + tid] * rsqrtf(var[m0 + tid] + 1e-5f);
        ssc[tid] = sc;
        ssh[tid] = beta[m0 + tid] - mean[m0 + tid] * sc;
    }
    #pragma unroll
    for (int p = 0; p < 32; p++) memst[p * 256 + tid] = 0.f;

    // epilogue thread coords
    const int en = tid & 63, ehl = tid >> 6;          // n, local h (0..3)
    const int hg = (m0 >> 5) + ehl;                   // global head slot 0..7

    for (int t = 0; t < T_; t++) {
        const float* Xb = X + (size_t)(t * B_ + b) * CN_;

        wmma::fragment<wmma::accumulator, 16, 16, 16, float> acc[2][2];
        #pragma unroll
        for (int i = 0; i < 2; i++)
            #pragma unroll
            for (int j = 0; j < 2; j++) wmma::fill_fragment(acc[i][j], 0.0f);

        __syncthreads();   // stage/W region reads from previous epilogue done

        // prologue: W slab 0 (1024 chunks), X slab 0 -> regs
        #pragma unroll
        for (int p = 0; p < 4; p++) {
            int ch = p * 256 + tid;
            int tm = ch >> 9, r = (ch >> 2) & 127, v = ch & 3;
            cp_async16(ws_base + (uint32_t)((tm * 128 + r) * LDW2 * 2 + v * 16),
                       (tm ? W1 : W0) + (m0 + r) * 256 + v * 8);
        }
        asm volatile("cp.async.commit_group;");
        float4 xr[2];
        #pragma unroll
        for (int p = 0; p < 2; p++) {
            int ch = p * 256 + tid;
            int r = ch >> 4, v = ch & 15;
            xr[p] = *(const float4*)(Xb + (size_t)r * N_ + n0 + v * 4);
        }

        for (int s = 0; s < NSLAB; s++) {
            const int buf = s & 1;

            // convert X regs -> Xs (2 fp16 terms)
            #pragma unroll
            for (int p = 0; p < 2; p++) {
                int ch = p * 256 + tid;
                int r = ch >> 4, v = ch & 15;
                float xin[4] = {xr[p].x, xr[p].y, xr[p].z, xr[p].w};
                __half t1[4], t2[4];
                #pragma unroll
                for (int j = 0; j < 4; j++) {
                    t1[j] = __float2half_rn(xin[j]);
                    t2[j] = __float2half_rn(xin[j] - __half2float(t1[j]));
                }
                *(uint2*)(Xs + 0 * KS * LDX3 + r * LDX3 + v * 4) = *(uint2*)t1;
                *(uint2*)(Xs + 1 * KS * LDX3 + r * LDX3 + v * 4) = *(uint2*)t2;
            }

            if (s < NSLAB - 1) {
                uint32_t wb = ws_base + (uint32_t)((buf ^ 1) * WBUF_BYTES);
                #pragma unroll
                for (int p = 0; p < 4; p++) {
                    int ch = p * 256 + tid;
                    int tm = ch >> 9, r = (ch >> 2) & 127, v = ch & 3;
                    cp_async16(wb + (uint32_t)((tm * 128 + r) * LDW2 * 2 + v * 16),
                               (tm ? W1 : W0) + (m0 + r) * 256 + (s + 1) * KS + v * 8);
                }
                asm volatile("cp.async.commit_group;");
                #pragma unroll
                for (int p = 0; p < 2; p++) {
                    int ch = p * 256 + tid;
                    int r = ch >> 4, v = ch & 15;
                    xr[p] = *(const float4*)(Xb + (size_t)((s + 1) * KS + r) * N_ + n0 + v * 4);
                }
                asm volatile("cp.async.wait_group 1;");
            } else {
                asm volatile("cp.async.wait_group 0;");
            }
            __syncthreads();

            const __half* Wb = (const __half*)(smem + MAIN_OFF + buf * WBUF_BYTES);
            #pragma unroll
            for (int ks = 0; ks < 2; ks++) {
                wmma::fragment<wmma::matrix_a, 16, 16, 16, __half, wmma::row_major> af[2][2];
                #pragma unroll
                for (int io = 0; io < 2; io++)
                    #pragma unroll
                    for (int tm = 0; tm < 2; tm++)
                        wmma::load_matrix_sync(af[io][tm],
                            Wb + tm * 128 * LDW2 + (wo * 32 + io * 16) * LDW2 + ks * 16, LDW2);
                #pragma unroll
                for (int jn = 0; jn < 2; jn++) {
                    wmma::fragment<wmma::matrix_b, 16, 16, 16, __half, wmma::row_major> bf[2];
                    #pragma unroll
                    for (int tm = 0; tm < 2; tm++)
                        wmma::load_matrix_sync(bf[tm],
                            Xs + tm * KS * LDX3 + ks * 16 * LDX3 + wn * 32 + jn * 16, LDX3);
                    #pragma unroll
                    for (int io = 0; io < 2; io++) {
                        wmma::mma_sync(acc[io][jn], af[io][0], bf[0], acc[io][jn]);
                        wmma::mma_sync(acc[io][jn], af[io][1], bf[0], acc[io][jn]);
                        wmma::mma_sync(acc[io][jn], af[io][0], bf[1], acc[io][jn]);
                    }
                }
            }
            __syncthreads();
        }

        // epilogue t: frags -> stage, then BN + LIF + bitpack
        #pragma unroll
        for (int io = 0; io < 2; io++)
            #pragma unroll
            for (int jn = 0; jn < 2; jn++)
                wmma::store_matrix_sync(stage + (wo * 32 + io * 16) * LDST + wn * 32 + jn * 16,
                                        acc[io][jn], LDST, wmma::mem_row_major);
        __syncthreads();

        unsigned bitsout = 0u;
        #pragma unroll
        for (int d = 0; d < 32; d++) {
            int o = ehl * 32 + d;
            float y = stage[o * LDST + en] * ssc[o] + ssh[o];
            float m = memst[o * 64 + en];
            m += (y - m) * 0.5f;
            if (m >= 1.0f) { bitsout |= (1u << d); m = 0.f; }
            memst[o * 64 + en] = m;
        }
        g_bits[proj][t * BHN + (b * 8 + hg) * N_ + n0 + en] = bitsout;
    }
}

// ===========================================================================
// Write v output: fully coalesced linear unpack of g_bits[2].
// ===========================================================================
__global__ __launch_bounds__(256)
void v_writer_kernel(float* __restrict__ vout)
{
    const int idx = blockIdx.x * 256 + threadIdx.x;
    unsigned w = g_bits[2][idx >> 5];
    vout[idx] = (float)((w >> (idx & 31)) & 1u);
}

// ===========================================================================
// Per (t,b,h): kv[d][e] = popc over n of k_d & v_e -> g_kvm (2 MB).
// ===========================================================================
__global__ __launch_bounds__(256)
void kv_only_kernel()
{
    __shared__ unsigned kb[1024], vb[1024];
    __shared__ unsigned krow[32][33], vrow[32][33];

    const int bid = blockIdx.x;    // (t*B+b)*8+h
    const int tid = threadIdx.x;
    const unsigned base = (unsigned)bid * 1024u;

    for (int i = tid; i < 1024; i += 256) {
        kb[i] = g_bits[1][base + i];
        vb[i] = g_bits[2][base + i];
    }
    __syncthreads();

    const int d = tid & 31;
    for (int w = tid >> 5; w < 32; w += 8) {
        unsigned rk = 0u, rv = 0u;
        #pragma unroll
        for (int j = 0; j < 32; j++) {
            rk |= ((kb[w * 32 + j] >> d) & 1u) << j;
            rv |= ((vb[w * 32 + j] >> d) & 1u) << j;
        }
        krow[d][w] = rk; vrow[d][w] = rv;
    }
    __syncthreads();

    for (int p = tid; p < 1024; p += 256) {
        int dd = p >> 5, e = p & 31;
        int s = 0;
        #pragma unroll
        for (int w = 0; w < 32; w++)
            s += __popc(krow[dd][w] & vrow[e][w]);
        g_kvm[base + p] = (float)s;
    }
}

// ===========================================================================
// attn-apply + LIF(0.5) + xs bitpack (no g_xa).
// ===========================================================================
__global__ __launch_bounds__(256)
void attn_lif_kernel()
{
    __shared__ float kvm[4][32][33];

    const int n0 = blockIdx.x * 256;
    const int h  = blockIdx.y;
    const int b  = blockIdx.z;
    const int tid = threadIdx.x;

    for (int i = tid; i < 4096; i += 256) {
        int t = i >> 10, p = i & 1023;
        kvm[t][p >> 5][p & 31] = g_kvm[(size_t)((t * B_ + b) * 8 + h) * 1024 + p];
    }
    __syncthreads();

    float mem[32];
    #pragma unroll
    for (int e = 0; e < 32; e++) mem[e] = 0.f;

    const int ob = (b * 8 + h) * N_ + n0 + tid;
    #pragma unroll
    for (int t = 0; t < 4; t++) {
        unsigned qm = g_bits[0][t * BHN + ob];
        unsigned bitsout = 0u;
        if (qm) {
            #pragma unroll
            for (int e = 0; e < 32; e++) {
                float s = 0.f;
                #pragma unroll
                for (int d = 0; d < 32; d++)
                    if (qm & (1u << d)) s += kvm[t][d][e];
                float y = 0.125f * s;
                mem[e] += (y - mem[e]) * 0.5f;
                if (mem[e] >= 0.5f) { bitsout |= (1u << e); mem[e] = 0.f; }
            }
        } else {
            #pragma unroll
            for (int e = 0; e < 32; e++) mem[e] *= 0.5f;
        }
        g_bits[3][t * BHN + ob] = bitsout;
    }
}

__global__ __launch_bounds__(256)
void wt_kernel(const float* __restrict__ pw)
{
    int idx = blockIdx.x * 256 + threadIdx.x;
    int o = idx & 255, c = idx >> 8;
    g_wt[c * 256 + o] = pw[o * 256 + c];
}

// ===========================================================================
// Fused sparse p-GEMM + bias + BN + LIF(1.0) -> out (unchanged)
// ===========================================================================
__global__ __launch_bounds__(256)
void sparse_p_out_kernel(const float* __restrict__ pb,
                         const float* __restrict__ pg,
                         const float* __restrict__ pbt,
                         const float* __restrict__ pm,
                         const float* __restrict__ pv,
                         float* __restrict__ out)
{
    __shared__ unsigned mw[4][8][64];
    __shared__ unsigned fl[4][64];
    __shared__ float s_sc[256], s_sh[256], s_bi[256];

    const int n0 = blockIdx.x * 64;
    const int b  = blockIdx.y;
    const int tid = threadIdx.x;

    {
        float sc = pg[tid] * rsqrtf(pv[tid] + 1e-5f);
        s_sc[tid] = sc;
        s_sh[tid] = pbt[tid] - pm[tid] * sc;
        s_bi[tid] = pb[tid];
    }
    for (int i = tid; i < 2048; i += 256) {
        int nn = i & 63, w = (i >> 6) & 7, t = i >> 9;
        mw[t][w][nn] = g_bits[3][t * BHN + (b * 8 + w) * N_ + n0 + nn];
    }
    __syncthreads();
    {
        int t = tid >> 6, nn = tid & 63;
        unsigned f = 0;
        #pragma unroll
        for (int w = 0; w < 8; w++) f |= mw[t][w][nn];
        fl[t][nn] = f;
    }
    __syncthreads();

    const int wi = tid >> 5, lane = tid & 31;
    for (int og = 0; og < 32; og++) {
        int o = og * 8 + wi;
        float sc = s_sc[o], sh = s_sh[o], bi = s_bi[o];
        float v0 = bi * sc + sh;
        #pragma unroll
        for (int nn2 = 0; nn2 < 2; nn2++) {
            int nn = nn2 * 32 + lane;
            float mem = 0.f;
            #pragma unroll
            for (int t = 0; t < 4; t++) {
                float y = v0;
                if (fl[t][nn]) {
                    float acc = 0.f;
                    #pragma unroll 1
                    for (int w = 0; w < 8; w++) {
                        unsigned m = mw[t][w][nn];
                        while (m) {
                            int d = __ffs(m) - 1;
                            m &= m - 1;
                            acc += g_wt[(w * 32 + d) * 256 + o];
                        }
                    }
                    y = (acc + bi) * sc + sh;
                }
                mem += (y - mem) * 0.5f;
                float s = (mem >= 1.0f) ? 1.0f : 0.0f;
                out[(size_t)t * BCN + (size_t)b * CN_ + (size_t)o * N_ + n0 + nn] = s;
                mem *= (1.0f - s);
            }
        }
    }
}

// ===========================================================================
extern "C" void kernel_launch(void* const* d_in, const int* in_sizes, int n_in,
                              void* d_out, int out_size)
{
    const float* x  = (const float*)d_in[0];
    const float* qw = (const float*)d_in[2];
    const float* qg = (const float*)d_in[3];
    const float* qb = (const float*)d_in[4];
    const float* qm = (const float*)d_in[5];
    const float* qv = (const float*)d_in[6];
    const float* kw = (const float*)d_in[7];
    const float* kg = (const float*)d_in[8];
    const float* kb = (const float*)d_in[9];
    const float* km = (const float*)d_in[10];
    const float* kv = (const float*)d_in[11];
    const float* vw = (const float*)d_in[12];
    const float* vg = (const float*)d_in[13];
    const float* vb = (const float*)d_in[14];
    const float* vm = (const float*)d_in[15];
    const float* vv = (const float*)d_in[16];
    const float* pw = (const float*)d_in[17];
    const float* pb = (const float*)d_in[18];
    const float* pg = (const float*)d_in[19];
    const float* pbt = (const float*)d_in[20];
    const float* pm = (const float*)d_in[21];
    const float* pv = (const float*)d_in[22];

    float* out  = (float*)d_out;
    float* vout = (out_size >= 2 * TBCN) ? out + TBCN : nullptr;

    static int smem_set = 0;
    if (!smem_set) {
        cudaFuncSetAttribute(gemm_lif_kernel,
                             cudaFuncAttributeMaxDynamicSharedMemorySize, SMEM_GT);
        smem_set = 1;
    }

    // one-shot weight preps
    wsplit_kernel<<<3 * C_ * C_ / 256, 256>>>(qw, kw, vw);
    wt_kernel<<<C_ * C_ / 256, 256>>>(pw);

    // fully fused q/k/v projection + BN + LIF + bitpack (g_y eliminated)
    dim3 tgrid(N_ / 64, C_ / 128, B_ * 3);
    gemm_lif_kernel<<<tgrid, 256, SMEM_GT>>>(x, qg, qb, qm, qv,
                                             kg, kb, km, kv, vg, vb, vm, vv);

    // v output (coalesced)
    if (vout)
        v_writer_kernel<<<TBCN / 256, 256>>>(vout);

    // kv matrices -> g_kvm
    kv_only_kernel<<<T_ * B_ * 8, 256>>>();

    // attn-apply + LIF(0.5) + xs bitpack
    attn_lif_kernel<<<dim3(N_ / 256, 8, B_), 256>>>();

    // fused sparse p-GEMM + BN + LIF(1.0) -> out
    sparse_p_out_kernel<<<dim3(N_ / 64, B_), 256>>>(pb, pg, pbt, pm, pv, out);
}

// round 13
// speedup vs baseline: 1.5314x; 1.5314x over previous
#include <cuda_runtime.h>
#include <cuda_fp16.h>
#include <mma.h>
#include <cstdint>

using namespace nvcuda;

#define T_ 4
#define B_ 16
#define C_ 256
#define N_ 1024
#define CN_ (C_*N_)          // 262144
#define BCN (B_*C_*N_)       // 4194304
#define TBCN (T_*BCN)        // 16777216
#define BHN (B_*8*N_)        // 131072
#define NBITS (T_*BHN)       // 524288 words per branch

// Scratch (device globals: allocation-free)
__device__ float    g_y[3][TBCN];     // post-BN pre-LIF activations for q,k,v
__device__ unsigned g_bits[4][NBITS]; // spike bitpacks: q,k,v, xs
__device__ float    g_kvm[T_*B_*8*1024]; // kv matrices: [t,b,h][32 d][32 e]
__device__ float    g_wt[C_*C_];      // p_w transposed
__device__ __align__(16) __half g_wsplit[3][2][C_*C_]; // fp16 2-term split of q/k/v W

__device__ __forceinline__ uint32_t smem_u32(const void* p) {
    return (uint32_t)__cvta_generic_to_shared(p);
}
__device__ __forceinline__ void cp_async16(uint32_t saddr, const void* g) {
    asm volatile("cp.async.ca.shared.global [%0], [%1], 16;" :: "r"(saddr), "l"(g));
}

// ===========================================================================
// One-shot: 2-term fp16 split of q/k/v weights (x ~ h1 + h2 to ~2^-22)
// ===========================================================================
__global__ __launch_bounds__(256)
void wsplit_kernel(const float* __restrict__ qw, const float* __restrict__ kw,
                   const float* __restrict__ vw)
{
    int idx = blockIdx.x * 256 + threadIdx.x;         // < 3*65536
    int proj = idx >> 16, e = idx & 65535;
    const float* W = proj == 0 ? qw : (proj == 1 ? kw : vw);
    float x = W[e];
    __half h1 = __float2half_rn(x);
    __half h2 = __float2half_rn(x - __half2float(h1));
    g_wsplit[proj][0][e] = h1;
    g_wsplit[proj][1][e] = h2;
}

// ===========================================================================
// Pipelined WMMA projection GEMM + BN (fp32-accurate, fp16 3-term split).
// One launch for q/k/v: blockIdx.z = tb*3 + proj.
// K in 8 slabs of 32; BOTH W and X double-buffered -> ONE sync per slab;
// converts/copies for slab s+1 overlap MMA of slab s.
// Block: 128(o) x 128(n); warp: 32(o) x 64(n).
// ===========================================================================
#define KS 32
#define NSLAB 8
#define LDW2 40                                    // 32 fp16 + 8 pad
#define LDX2 136                                   // 128 fp16 + 8 pad
#define WBUF_BYTES (2*128*LDW2*2)                  // 20480
#define XBUF_BYTES (2*KS*LDX2*2)                   // 17408
#define XS_OFF (2*WBUF_BYTES)                      // 40960
#define SMEM_GT (XS_OFF + 2*XBUF_BYTES)            // 75776 (stage 67584 unions at 0)

__global__ __launch_bounds__(256, 2)
void gemm_wmma_kernel(const float* __restrict__ X,
                      const float* __restrict__ qg, const float* __restrict__ qb,
                      const float* __restrict__ qm, const float* __restrict__ qv,
                      const float* __restrict__ kg, const float* __restrict__ kb,
                      const float* __restrict__ km, const float* __restrict__ kv,
                      const float* __restrict__ vg, const float* __restrict__ vb,
                      const float* __restrict__ vm, const float* __restrict__ vv)
{
    extern __shared__ __align__(16) char smem[];
    float* stage = (float*)smem;               // [128][132] (epilogue reuse)

    const int tid = threadIdx.x, wid = tid >> 5;
    const int n0 = blockIdx.x * 128;
    const int m0 = blockIdx.y * 128;
    const int proj = blockIdx.z % 3;
    const int tb = blockIdx.z / 3;
    const float* Xb = X + (size_t)tb * CN_;
    float* Yb = g_y[proj] + (size_t)tb * CN_;

    const float* gamma = proj == 0 ? qg : (proj == 1 ? kg : vg);
    const float* beta  = proj == 0 ? qb : (proj == 1 ? kb : vb);
    const float* mean  = proj == 0 ? qm : (proj == 1 ? km : vm);
    const float* var   = proj == 0 ? qv : (proj == 1 ? kv : vv);
    const __half* W0 = g_wsplit[proj][0];
    const __half* W1 = g_wsplit[proj][1];

    const int wo = wid & 3;    // o-group (32 rows)
    const int wn = wid >> 2;   // n-group (64 cols)

    const uint32_t ws_base = smem_u32(smem);
    const int xr_r = tid >> 5;       // X ldg row base (rows step by 8)
    const int xr_v = tid & 31;
    // W cp.async coords: ch = p*256+tid < 1024: tm=ch>>9, r=(ch>>2)&127, v=ch&3
    const int w_tm = (2 * 256 <= tid + 0) ? 1 : 0; // unused; computed per p below

    wmma::fragment<wmma::accumulator, 16, 16, 16, float> acc[2][4];
    #pragma unroll
    for (int i = 0; i < 2; i++)
        #pragma unroll
        for (int j = 0; j < 4; j++) wmma::fill_fragment(acc[i][j], 0.0f);

    // ---- prologue ----
    // W(0) -> Wbuf0
    #pragma unroll
    for (int p = 0; p < 4; p++) {
        int ch = p * 256 + tid;
        int tm = ch >> 9, r = (ch >> 2) & 127, v = ch & 3;
        cp_async16(ws_base + (uint32_t)((tm * 128 + r) * LDW2 * 2 + v * 16),
                   (tm ? W1 : W0) + (m0 + r) * 256 + v * 8);
    }
    asm volatile("cp.async.commit_group;");
    // X(0) -> regs -> Xs0
    float4 xr[4];
    #pragma unroll
    for (int p = 0; p < 4; p++)
        xr[p] = *(const float4*)(Xb + (size_t)(xr_r + p * 8) * N_ + n0 + xr_v * 4);
    {
        __half* Xs0 = (__half*)(smem + XS_OFF);
        #pragma unroll
        for (int p = 0; p < 4; p++) {
            int r = xr_r + p * 8;
            float xin[4] = {xr[p].x, xr[p].y, xr[p].z, xr[p].w};
            __half t1[4], t2[4];
            #pragma unroll
            for (int j = 0; j < 4; j++) {
                t1[j] = __float2half_rn(xin[j]);
                t2[j] = __float2half_rn(xin[j] - __half2float(t1[j]));
            }
            *(uint2*)(Xs0 + 0 * KS * LDX2 + r * LDX2 + xr_v * 4) = *(uint2*)t1;
            *(uint2*)(Xs0 + 1 * KS * LDX2 + r * LDX2 + xr_v * 4) = *(uint2*)t2;
        }
    }
    // X(1) -> regs (converted inside slab 0)
    #pragma unroll
    for (int p = 0; p < 4; p++)
        xr[p] = *(const float4*)(Xb + (size_t)(KS + xr_r + p * 8) * N_ + n0 + xr_v * 4);
    asm volatile("cp.async.wait_group 0;");   // W(0) resident
    __syncthreads();

    for (int s = 0; s < NSLAB; s++) {
        const int buf = s & 1;

        if (s < NSLAB - 1) {
            // W(s+1) -> Wbuf[buf^1] (read last at s-1; sync'd)
            uint32_t wb = ws_base + (uint32_t)((buf ^ 1) * WBUF_BYTES);
            #pragma unroll
            for (int p = 0; p < 4; p++) {
                int ch = p * 256 + tid;
                int tm = ch >> 9, r = (ch >> 2) & 127, v = ch & 3;
                cp_async16(wb + (uint32_t)((tm * 128 + r) * LDW2 * 2 + v * 16),
                           (tm ? W1 : W0) + (m0 + r) * 256 + (s + 1) * KS + v * 8);
            }
            asm volatile("cp.async.commit_group;");
            // convert X(s+1) regs -> Xs[buf^1]
            __half* Xsn = (__half*)(smem + XS_OFF + (buf ^ 1) * XBUF_BYTES);
            #pragma unroll
            for (int p = 0; p < 4; p++) {
                int r = xr_r + p * 8;
                float xin[4] = {xr[p].x, xr[p].y, xr[p].z, xr[p].w};
                __half t1[4], t2[4];
                #pragma unroll
                for (int j = 0; j < 4; j++) {
                    t1[j] = __float2half_rn(xin[j]);
                    t2[j] = __float2half_rn(xin[j] - __half2float(t1[j]));
                }
                *(uint2*)(Xsn + 0 * KS * LDX2 + r * LDX2 + xr_v * 4) = *(uint2*)t1;
                *(uint2*)(Xsn + 1 * KS * LDX2 + r * LDX2 + xr_v * 4) = *(uint2*)t2;
            }
            // LDG X(s+2) -> regs
            if (s < NSLAB - 2) {
                #pragma unroll
                for (int p = 0; p < 4; p++)
                    xr[p] = *(const float4*)(Xb + (size_t)((s + 2) * KS + xr_r + p * 8) * N_ + n0 + xr_v * 4);
            }
        }

        // ---- MMA on slab s (Wbuf[buf], Xs[buf]) ----
        const __half* Wb = (const __half*)(smem + buf * WBUF_BYTES);
        const __half* Xs = (const __half*)(smem + XS_OFF + buf * XBUF_BYTES);
        #pragma unroll
        for (int ks = 0; ks < 2; ks++) {
            wmma::fragment<wmma::matrix_a, 16, 16, 16, __half, wmma::row_major> af[2][2];
            #pragma unroll
            for (int io = 0; io < 2; io++)
                #pragma unroll
                for (int tm = 0; tm < 2; tm++)
                    wmma::load_matrix_sync(af[io][tm],
                        Wb + tm * 128 * LDW2 + (wo * 32 + io * 16) * LDW2 + ks * 16, LDW2);
            #pragma unroll
            for (int jn = 0; jn < 4; jn++) {
                wmma::fragment<wmma::matrix_b, 16, 16, 16, __half, wmma::row_major> bf[2];
                #pragma unroll
                for (int tm = 0; tm < 2; tm++)
                    wmma::load_matrix_sync(bf[tm],
                        Xs + tm * KS * LDX2 + ks * 16 * LDX2 + wn * 64 + jn * 16, LDX2);
                #pragma unroll
                for (int io = 0; io < 2; io++) {
                    wmma::mma_sync(acc[io][jn], af[io][0], bf[0], acc[io][jn]);
                    wmma::mma_sync(acc[io][jn], af[io][1], bf[0], acc[io][jn]);
                    wmma::mma_sync(acc[io][jn], af[io][0], bf[1], acc[io][jn]);
                }
            }
        }

        if (s < NSLAB - 1)
            asm volatile("cp.async.wait_group 0;");  // W(s+1) resident
        __syncthreads();
    }

    // --- epilogue: frags -> smem stage, then BN + coalesced writes ---
    #pragma unroll
    for (int io = 0; io < 2; io++)
        #pragma unroll
        for (int jn = 0; jn < 4; jn++)
            wmma::store_matrix_sync(stage + (wo * 32 + io * 16) * 132 + wn * 64 + jn * 16,
                                    acc[io][jn], 132, wmma::mem_row_major);
    __syncthreads();

    #pragma unroll
    for (int p = 0; p < 16; p++) {
        int idx = p * 256 + tid;
        int row = idx >> 5, c4 = (idx & 31) * 4;
        int o = m0 + row;
        float sc = gamma[o] * rsqrtf(var[o] + 1e-5f);
        float sh = beta[o] - mean[o] * sc;
        const float* sp = stage + row * 132 + c4;
        float4 yv = make_float4(sp[0] * sc + sh, sp[1] * sc + sh,
                                sp[2] * sc + sh, sp[3] * sc + sh);
        *(float4*)(Yb + (size_t)o * N_ + n0 + c4) = yv;
    }
}

// ===========================================================================
// LIF over T (vth=1) + bitpack for q,k,v. One thread per (b,h,n).
// ===========================================================================
__global__ __launch_bounds__(256)
void lif_pack_kernel()
{
    const int proj = blockIdx.y;
    const int idx = blockIdx.x * 256 + threadIdx.x;  // < B*8*N = 131072
    const int n = idx & (N_ - 1);
    const int h = (idx >> 10) & 7;
    const int b = idx >> 13;
    const float* Y = g_y[proj];

    unsigned bits[4] = {0u, 0u, 0u, 0u};
    for (int d = 0; d < 32; d++) {
        const float* p = Y + (size_t)b * CN_ + (size_t)(h * 32 + d) * N_ + n;
        float mem = 0.f;
        #pragma unroll
        for (int t = 0; t < 4; t++) {
            float y = p[(size_t)t * BCN];
            mem += (y - mem) * 0.5f;
            if (mem >= 1.0f) { bits[t] |= (1u << d); mem = 0.f; }
        }
    }
    const int ob = (b * 8 + h) * N_ + n;
    #pragma unroll
    for (int t = 0; t < 4; t++)
        g_bits[proj][t * BHN + ob] = bits[t];
}

// ===========================================================================
// v output: 4 consecutive bits of one word -> one float4; fully coalesced.
// ===========================================================================
__global__ __launch_bounds__(256)
void v_writer_kernel(float4* __restrict__ vout)
{
    const int idx = blockIdx.x * 256 + threadIdx.x;   // < TBCN/4
    unsigned w = g_bits[2][idx >> 3];
    int sh = (idx & 7) * 4;
    vout[idx] = make_float4((float)((w >> sh) & 1u), (float)((w >> (sh + 1)) & 1u),
                            (float)((w >> (sh + 2)) & 1u), (float)((w >> (sh + 3)) & 1u));
}

// ===========================================================================
// Per (t,b,h): kv[d][e] = popc over n of k_d & v_e -> g_kvm (2 MB).
// ===========================================================================
__global__ __launch_bounds__(256)
void kv_only_kernel()
{
    __shared__ unsigned kb[1024], vb[1024];
    __shared__ unsigned krow[32][33], vrow[32][33];

    const int bid = blockIdx.x;    // (t*B+b)*8+h
    const int tid = threadIdx.x;
    const unsigned base = (unsigned)bid * 1024u;

    for (int i = tid; i < 1024; i += 256) {
        kb[i] = g_bits[1][base + i];
        vb[i] = g_bits[2][base + i];
    }
    __syncthreads();

    const int d = tid & 31;
    for (int w = tid >> 5; w < 32; w += 8) {
        unsigned rk = 0u, rv = 0u;
        #pragma unroll
        for (int j = 0; j < 32; j++) {
            rk |= ((kb[w * 32 + j] >> d) & 1u) << j;
            rv |= ((vb[w * 32 + j] >> d) & 1u) << j;
        }
        krow[d][w] = rk; vrow[d][w] = rv;
    }
    __syncthreads();

    for (int p = tid; p < 1024; p += 256) {
        int dd = p >> 5, e = p & 31;
        int s = 0;
        #pragma unroll
        for (int w = 0; w < 32; w++)
            s += __popc(krow[dd][w] & vrow[e][w]);
        g_kvm[base + p] = (float)s;
    }
}

// ===========================================================================
// attn-apply + LIF(0.5) + xs bitpack (no g_xa).
// ===========================================================================
__global__ __launch_bounds__(256)
void attn_lif_kernel()
{
    __shared__ float kvm[4][32][33];

    const int n0 = blockIdx.x * 256;
    const int h  = blockIdx.y;
    const int b  = blockIdx.z;
    const int tid = threadIdx.x;

    for (int i = tid; i < 4096; i += 256) {
        int t = i >> 10, p = i & 1023;
        kvm[t][p >> 5][p & 31] = g_kvm[(size_t)((t * B_ + b) * 8 + h) * 1024 + p];
    }
    __syncthreads();

    float mem[32];
    #pragma unroll
    for (int e = 0; e < 32; e++) mem[e] = 0.f;

    const int ob = (b * 8 + h) * N_ + n0 + tid;
    #pragma unroll
    for (int t = 0; t < 4; t++) {
        unsigned qm = g_bits[0][t * BHN + ob];
        unsigned bitsout = 0u;
        if (qm) {
            #pragma unroll
            for (int e = 0; e < 32; e++) {
                float s = 0.f;
                #pragma unroll
                for (int d = 0; d < 32; d++)
                    if (qm & (1u << d)) s += kvm[t][d][e];
                float y = 0.125f * s;
                mem[e] += (y - mem[e]) * 0.5f;
                if (mem[e] >= 0.5f) { bitsout |= (1u << e); mem[e] = 0.f; }
            }
        } else {
            #pragma unroll
            for (int e = 0; e < 32; e++) mem[e] *= 0.5f;
        }
        g_bits[3][t * BHN + ob] = bitsout;
    }
}

__global__ __launch_bounds__(256)
void wt_kernel(const float* __restrict__ pw)
{
    int idx = blockIdx.x * 256 + threadIdx.x;
    int o = idx & 255, c = idx >> 8;
    g_wt[c * 256 + o] = pw[o * 256 + c];
}

// ===========================================================================
// Fused sparse p-GEMM + bias + BN + LIF(1.0) -> out (unchanged)
// ===========================================================================
__global__ __launch_bounds__(256)
void sparse_p_out_kernel(const float* __restrict__ pb,
                         const float* __restrict__ pg,
                         const float* __restrict__ pbt,
                         const float* __restrict__ pm,
                         const float* __restrict__ pv,
                         float* __restrict__ out)
{
    __shared__ unsigned mw[4][8][64];
    __shared__ unsigned fl[4][64];
    __shared__ float s_sc[256], s_sh[256], s_bi[256];

    const int n0 = blockIdx.x * 64;
    const int b  = blockIdx.y;
    const int tid = threadIdx.x;

    {
        float sc = pg[tid] * rsqrtf(pv[tid] + 1e-5f);
        s_sc[tid] = sc;
        s_sh[tid] = pbt[tid] - pm[tid] * sc;
        s_bi[tid] = pb[tid];
    }
    for (int i = tid; i < 2048; i += 256) {
        int nn = i & 63, w = (i >> 6) & 7, t = i >> 9;
        mw[t][w][nn] = g_bits[3][t * BHN + (b * 8 + w) * N_ + n0 + nn];
    }
    __syncthreads();
    {
        int t = tid >> 6, nn = tid & 63;
        unsigned f = 0;
        #pragma unroll
        for (int w = 0; w < 8; w++) f |= mw[t][w][nn];
        fl[t][nn] = f;
    }
    __syncthreads();

    const int wi = tid >> 5, lane = tid & 31;
    for (int og = 0; og < 32; og++) {
        int o = og * 8 + wi;
        float sc = s_sc[o], sh = s_sh[o], bi = s_bi[o];
        float v0 = bi * sc + sh;
        #pragma unroll
        for (int nn2 = 0; nn2 < 2; nn2++) {
            int nn = nn2 * 32 + lane;
            float mem = 0.f;
            #pragma unroll
            for (int t = 0; t < 4; t++) {
                float y = v0;
                if (fl[t][nn]) {
                    float acc = 0.f;
                    #pragma unroll 1
                    for (int w = 0; w < 8; w++) {
                        unsigned m = mw[t][w][nn];
                        while (m) {
                            int d = __ffs(m) - 1;
                            m &= m - 1;
                            acc += g_wt[(w * 32 + d) * 256 + o];
                        }
                    }
                    y = (acc + bi) * sc + sh;
                }
                mem += (y - mem) * 0.5f;
                float s = (mem >= 1.0f) ? 1.0f : 0.0f;
                out[(size_t)t * BCN + (size_t)b * CN_ + (size_t)o * N_ + n0 + nn] = s;
                mem *= (1.0f - s);
            }
        }
    }
}

// ===========================================================================
extern "C" void kernel_launch(void* const* d_in, const int* in_sizes, int n_in,
                              void* d_out, int out_size)
{
    const float* x  = (const float*)d_in[0];
    const float* qw = (const float*)d_in[2];
    const float* qg = (const float*)d_in[3];
    const float* qb = (const float*)d_in[4];
    const float* qm = (const float*)d_in[5];
    const float* qv = (const float*)d_in[6];
    const float* kw = (const float*)d_in[7];
    const float* kg = (const float*)d_in[8];
    const float* kb = (const float*)d_in[9];
    const float* km = (const float*)d_in[10];
    const float* kv = (const float*)d_in[11];
    const float* vw = (const float*)d_in[12];
    const float* vg = (const float*)d_in[13];
    const float* vb = (const float*)d_in[14];
    const float* vm = (const float*)d_in[15];
    const float* vv = (const float*)d_in[16];
    const float* pw = (const float*)d_in[17];
    const float* pb = (const float*)d_in[18];
    const float* pg = (const float*)d_in[19];
    const float* pbt = (const float*)d_in[20];
    const float* pm = (const float*)d_in[21];
    const float* pv = (const float*)d_in[22];

    float* out  = (float*)d_out;
    float* vout = (out_size >= 2 * TBCN) ? out + TBCN : nullptr;

    static int smem_set = 0;
    if (!smem_set) {
        cudaFuncSetAttribute(gemm_wmma_kernel,
                             cudaFuncAttributeMaxDynamicSharedMemorySize, SMEM_GT);
        smem_set = 1;
    }

    // one-shot weight preps
    wsplit_kernel<<<3 * C_ * C_ / 256, 256>>>(qw, kw, vw);
    wt_kernel<<<C_ * C_ / 256, 256>>>(pw);

    // q,k,v projections: one pipelined wmma launch (fp16 3-term, X+W dbl-buf)
    dim3 tgrid(N_ / 128, C_ / 128, T_ * B_ * 3);
    gemm_wmma_kernel<<<tgrid, 256, SMEM_GT>>>(x, qg, qb, qm, qv,
                                              kg, kb, km, kv, vg, vb, vm, vv);

    // LIF(1.0) + bitpack for q,k,v
    lif_pack_kernel<<<dim3(BHN / 256, 3), 256>>>();

    // v output (coalesced float4)
    if (vout)
        v_writer_kernel<<<TBCN / 1024, 256>>>((float4*)vout);

    // kv matrices -> g_kvm
    kv_only_kernel<<<T_ * B_ * 8, 256>>>();

    // attn-apply + LIF(0.5) + xs bitpack
    attn_lif_kernel<<<dim3(N_ / 256, 8, B_), 256>>>();

    // fused sparse p-GEMM + BN + LIF(1.0) -> out
    sparse_p_out_kernel<<<dim3(N_ / 64, B_), 256>>>(pb, pg, pbt, pm, pv, out);
}